// round 17
// baseline (speedup 1.0000x reference)
#include <cuda_runtime.h>
#include <cuda_fp16.h>
#include <mma.h>
#include <cstdint>

using namespace nvcuda;

#define Bb 16
#define Cc 256
#define Ss 64
#define Hh 8
#define Dd 32

typedef __half hf;

// ---------------------------------------------------------------------------
// Scratch (all intermediates fp16, rounded at producers; fp32 accum in MMA)
// ---------------------------------------------------------------------------
__device__ hf g_pool[4][Cc * Bb * Ss];               // [c][b*64+s]  (A^T)
__device__ hf g_qkh[4][Bb * Hh * Ss * Dd];           // [b][head][s][d]
__device__ hf g_vconv[(size_t)Bb * Cc * 4096];       // [b][c][hw] (A^T)
__device__ hf g_v[(size_t)Bb * Hh * 4096 * 32];      // [b][head][hw][dv]
__device__ hf g_r[(size_t)Bb * Hh * Ss * Ss * Dd];   // [b][head][h][w*32+dv]
__device__ hf g_r2[(size_t)Bb * 4096 * Cc];          // [b][m=hw][k]
__device__ hf g_wh[6][Cc * Cc];                      // pre-rounded weights

__device__ __forceinline__ hf to_h(float x) { return __float2half_rn(x); }

__device__ __forceinline__ void cp_async16(void* smem, const void* gmem) {
    uint32_t s = (uint32_t)__cvta_generic_to_shared(smem);
    asm volatile("cp.async.cg.shared.global [%0], [%1], 16;" :: "r"(s), "l"(gmem));
}
#define CP_COMMIT() asm volatile("cp.async.commit_group;" ::: "memory")
#define CP_WAIT(n)  asm volatile("cp.async.wait_group %0;" :: "n"(n) : "memory")

// ---------------------------------------------------------------------------
// Inline attention: scores (fp16 wmma) + softmax for one bh, 256 threads.
// Writes the fp16 attention matrix into dst (ld 72). sc: fp32 [64][68] scratch.
// Arithmetic identical to the old attn_kernel.
// ---------------------------------------------------------------------------
__device__ __forceinline__ void attn_inline(
    const hf* __restrict__ q, const hf* __restrict__ k,
    const float* __restrict__ Bm, hf* __restrict__ dst, float* __restrict__ sc)
{
    const int tid = threadIdx.x;
    {
        const int wid = tid >> 5;
        const int wm = wid >> 1;
        const int wn = wid & 1;
        wmma::fragment<wmma::accumulator, 16, 16, 16, float> acc[2];
        wmma::fill_fragment(acc[0], 0.f);
        wmma::fill_fragment(acc[1], 0.f);
#pragma unroll
        for (int d0 = 0; d0 < 32; d0 += 16) {
            wmma::fragment<wmma::matrix_a, 16, 16, 16, half, wmma::row_major> af;
            wmma::load_matrix_sync(af, q + (size_t)(wm * 16) * 32 + d0, 32);
            wmma::fragment<wmma::matrix_b, 16, 16, 16, half, wmma::col_major> bf_[2];
            wmma::load_matrix_sync(bf_[0], k + (size_t)(wn * 32) * 32 + d0, 32);
            wmma::load_matrix_sync(bf_[1], k + (size_t)(wn * 32 + 16) * 32 + d0, 32);
            wmma::mma_sync(acc[0], af, bf_[0], acc[0]);
            wmma::mma_sync(acc[1], af, bf_[1], acc[1]);
        }
        wmma::store_matrix_sync(&sc[wm * 16 * 68 + wn * 32], acc[0], 68,
                                wmma::mem_row_major);
        wmma::store_matrix_sync(&sc[wm * 16 * 68 + wn * 32 + 16], acc[1], 68,
                                wmma::mem_row_major);
    }
    __syncthreads();
    {
        const float scale = 0.17677669529663687f;
        const int i = tid >> 2;
        const int qq = tid & 3;
        float s[16];
        float mx = -1e30f;
#pragma unroll
        for (int jj = 0; jj < 16; jj += 4) {
            const int j = qq * 16 + jj;
            const float4 c4 = *reinterpret_cast<const float4*>(&sc[i * 68 + j]);
            const float4 b4 = *reinterpret_cast<const float4*>(&Bm[i * 64 + j]);
            s[jj + 0] = c4.x * scale + b4.x;
            s[jj + 1] = c4.y * scale + b4.y;
            s[jj + 2] = c4.z * scale + b4.z;
            s[jj + 3] = c4.w * scale + b4.w;
            mx = fmaxf(mx, fmaxf(fmaxf(s[jj], s[jj + 1]), fmaxf(s[jj + 2], s[jj + 3])));
        }
        mx = fmaxf(mx, __shfl_xor_sync(0xffffffffu, mx, 1));
        mx = fmaxf(mx, __shfl_xor_sync(0xffffffffu, mx, 2));
        float sum = 0.f;
#pragma unroll
        for (int jj = 0; jj < 16; jj++) { s[jj] = __expf(s[jj] - mx); sum += s[jj]; }
        sum += __shfl_xor_sync(0xffffffffu, sum, 1);
        sum += __shfl_xor_sync(0xffffffffu, sum, 2);
        const float r = 1.f / sum;
#pragma unroll
        for (int jj = 0; jj < 16; jj += 4) {
            const int j = qq * 16 + jj;
            __half2 lo, hi;
            lo.x = to_h(s[jj + 0] * r); lo.y = to_h(s[jj + 1] * r);
            hi.x = to_h(s[jj + 2] * r); hi.y = to_h(s[jj + 3] * r);
            uint2 pk;
            pk.x = *reinterpret_cast<uint32_t*>(&lo);
            pk.y = *reinterpret_cast<uint32_t*>(&hi);
            *reinterpret_cast<uint2*>(&dst[i * 72 + j]) = pk;
        }
    }
}

// ---------------------------------------------------------------------------
// Kernel 1: fused V dwconv + analytic pooled q/k branches + weight rounding.
// ---------------------------------------------------------------------------
__global__ void __launch_bounds__(256) conv_fused_kernel(
    const float* __restrict__ x,
    const float* __restrict__ wv,  const float* __restrict__ bv,
    const float* __restrict__ wqh, const float* __restrict__ bqh,
    const float* __restrict__ wkh, const float* __restrict__ bkh,
    const float* __restrict__ wqw, const float* __restrict__ bqw,
    const float* __restrict__ wkw, const float* __restrict__ bkw,
    const float* __restrict__ fqh, const float* __restrict__ fkh,
    const float* __restrict__ fqw, const float* __restrict__ fkw,
    const float* __restrict__ fv,  const float* __restrict__ fo)
{
    const int tid = threadIdx.x;

    if (blockIdx.y == Bb) {
        const int i = blockIdx.x * 256 + tid;
        g_wh[0][i] = to_h(fqh[i]);
        g_wh[1][i] = to_h(fkh[i]);
        g_wh[2][i] = to_h(fqw[i]);
        g_wh[3][i] = to_h(fkw[i]);
        g_wh[4][i] = to_h(fv[i]);
        g_wh[5][i] = to_h(fo[i]);
        return;
    }

    const int c = blockIdx.x;
    const int b = blockIdx.y;

    __shared__ float xs[66][66];
    __shared__ float rowp[2][64], colp[4][64];
    __shared__ float T[64];
    __shared__ float wsm[4][9];
    __shared__ float bsm[4];

    for (int i = tid; i < 66 * 66; i += 256) (&xs[0][0])[i] = 0.f;
    __syncthreads();

    const float4* xp4 = reinterpret_cast<const float4*>(x + ((size_t)b * Cc + c) * 4096);
    for (int i = tid; i < 1024; i += 256) {
        const float4 v = xp4[i];
        const int e = i * 4;
        float* d = &xs[(e >> 6) + 1][(e & 63) + 1];
        d[0] = v.x; d[1] = v.y; d[2] = v.z; d[3] = v.w;
    }

    if (tid < 9)        wsm[0][tid]      = wqh[c * 9 + tid];
    else if (tid < 18)  wsm[1][tid - 9]  = wkh[c * 9 + tid - 9];
    else if (tid < 27)  wsm[2][tid - 18] = wqw[c * 9 + tid - 18];
    else if (tid < 36)  wsm[3][tid - 27] = wkw[c * 9 + tid - 27];
    if (tid == 36) bsm[0] = bqh[c];
    if (tid == 37) bsm[1] = bkh[c];
    if (tid == 38) bsm[2] = bqw[c];
    if (tid == 39) bsm[3] = bkw[c];

    float w[9];
#pragma unroll
    for (int i = 0; i < 9; i++) w[i] = wv[c * 9 + i];
    const float bias = bv[c];
    __syncthreads();

    const int wcol = tid & 63;
    const int hgrp = tid >> 6;
    hf* op = g_vconv + ((size_t)b * Cc + c) * 4096;

    float colacc = 0.f;
    for (int k = 0; k < 16; k++) {
        const int h = hgrp * 16 + k;
        float s = bias;
#pragma unroll
        for (int dy = 0; dy < 3; dy++)
#pragma unroll
            for (int dx = 0; dx < 3; dx++)
                s += w[dy * 3 + dx] * xs[h + dy][wcol + dx];
        op[h * 64 + wcol] = to_h(s);
        const float v = xs[h + 1][wcol + 1];
        colacc += v;
        float rsum = v;
#pragma unroll
        for (int off = 16; off; off >>= 1)
            rsum += __shfl_down_sync(0xffffffffu, rsum, off);
        if ((tid & 31) == 0) rowp[(tid >> 5) & 1][h] = rsum;
    }
    colp[hgrp][wcol] = colacc;
    __syncthreads();
    if (tid < 64) T[tid] = colp[0][tid] + colp[1][tid] + colp[2][tid] + colp[3][tid];
    __syncthreads();

    if (tid < 64) {
        const int s = tid;
        float o0 = 0.f, o1 = 0.f, o2 = 0.f, o3 = 0.f;
#pragma unroll
        for (int d = 0; d < 3; d++) {
            const int r = s + d - 1;
            if (r >= 0 && r < 64) {
                const float Sv = rowp[0][r] + rowp[1][r];
                const float eL = xs[r + 1][1], eR = xs[r + 1][64];
                o0 += (wsm[0][d*3] + wsm[0][d*3+1] + wsm[0][d*3+2]) * Sv
                    - wsm[0][d*3] * eR - wsm[0][d*3+2] * eL;
                o1 += (wsm[1][d*3] + wsm[1][d*3+1] + wsm[1][d*3+2]) * Sv
                    - wsm[1][d*3] * eR - wsm[1][d*3+2] * eL;
                const float Tv = T[r];
                const float eT = xs[1][r + 1], eB = xs[64][r + 1];
                o2 += (wsm[2][d] + wsm[2][3+d] + wsm[2][6+d]) * Tv
                    - wsm[2][d] * eB - wsm[2][6+d] * eT;
                o3 += (wsm[3][d] + wsm[3][3+d] + wsm[3][6+d]) * Tv
                    - wsm[3][d] * eB - wsm[3][6+d] * eT;
            }
        }
        const float inv = 1.f / 64.f;
        const int mi = b * 64 + s;
        g_pool[0][c * 1024 + mi] = to_h(o0 * inv + bsm[0]);
        g_pool[1][c * 1024 + mi] = to_h(o1 * inv + bsm[1]);
        g_pool[2][c * 1024 + mi] = to_h(o2 * inv + bsm[2]);
        g_pool[3][c * 1024 + mi] = to_h(o3 * inv + bsm[3]);
    }
}

// ---------------------------------------------------------------------------
// Unified fp16 wmma GEMM, cp.async double buffered, BK=64 (4 iterations).
// No sbias staging: zero-init acc, bias added in the smem epilogue. 4 CTAs/SM.
// ---------------------------------------------------------------------------
#define APB 4608            // A elems per buffer (64 x 72)
#define WPB 9216            // W elems per buffer (128 x 72)

template <int MODE>
__global__ void __launch_bounds__(128, 4) wmma_gemm_kernel(
    const float* __restrict__ b0, const float* __restrict__ b1,
    const float* __restrict__ b2, const float* __restrict__ b3,
    const float* __restrict__ bv, float* __restrict__ outp)
{
    __shared__ __align__(16) unsigned char smem_raw[2 * APB * 2 + 2 * WPB * 2];
    hf* Asm = reinterpret_cast<hf*>(smem_raw);
    hf* Wsm = reinterpret_cast<hf*>(smem_raw + 2 * APB * 2);
    float* Cs = reinterpret_cast<float*>(smem_raw);   // epilogue staging [64][132]

    const int tid = threadIdx.x;
    const int wid = tid >> 5;
    const int wm = wid >> 1;
    const int wn = wid & 1;
    const int nb = blockIdx.y * 128;
    const int z = blockIdx.z;

    const hf* A;
    const hf* W;
    const float* bias;
    int ldA, m0;
    bool isqk = false;
    int qkbr = 0;
    if constexpr (MODE == 1) {
        if (z < 16) {
            A = g_vconv + (size_t)z * 1048576; ldA = 4096;
            W = g_wh[4]; bias = bv; m0 = blockIdx.x * 64;
        } else {
            isqk = true;
            qkbr = blockIdx.x >> 4;
            A = g_pool[qkbr]; ldA = 1024;
            W = g_wh[qkbr];
            bias = (qkbr == 0) ? b0 : (qkbr == 1) ? b1 : (qkbr == 2) ? b2 : b3;
            m0 = (blockIdx.x & 15) * 64;
        }
    } else {
        A = g_r2 + (size_t)z * 1048576; ldA = 256;
        W = g_wh[5]; bias = b0; m0 = blockIdx.x * 64;
    }

    auto load_tiles = [&](int k0, int buf) {
        hf* As = Asm + buf * APB;
        hf* Ws = Wsm + buf * WPB;
#pragma unroll
        for (int i = 0; i < 4; i++) {
            const int f = tid + 128 * i;
            if constexpr (MODE == 1) {
                const int k = f >> 3, mq = f & 7;
                cp_async16(As + k * 72 + mq * 8,
                           A + (size_t)(k0 + k) * ldA + m0 + mq * 8);
            } else {
                const int m = f >> 3, kq = f & 7;
                cp_async16(As + m * 72 + kq * 8,
                           A + (size_t)(m0 + m) * 256 + k0 + kq * 8);
            }
        }
#pragma unroll
        for (int i = 0; i < 8; i++) {
            const int f = tid + 128 * i;
            const int n = f >> 3, kq = f & 7;
            cp_async16(Ws + n * 72 + kq * 8,
                       W + (size_t)(nb + n) * 256 + k0 + kq * 8);
        }
        CP_COMMIT();
    };

    load_tiles(0, 0);

    wmma::fragment<wmma::accumulator, 16, 16, 16, float> acc[2][4];
#pragma unroll
    for (int i = 0; i < 2; i++)
#pragma unroll
        for (int j = 0; j < 4; j++)
            wmma::fill_fragment(acc[i][j], 0.f);

    int buf = 0;
    for (int it = 0; it < 4; it++) {
        if (it < 3) load_tiles((it + 1) * 64, buf ^ 1);
        if (it < 3) { CP_WAIT(1); } else { CP_WAIT(0); }
        __syncthreads();

        hf* As = Asm + buf * APB;
        hf* Ws = Wsm + buf * WPB;
#pragma unroll
        for (int kk = 0; kk < 64; kk += 16) {
            wmma::fragment<wmma::matrix_b, 16, 16, 16, half, wmma::col_major> bf_[4];
#pragma unroll
            for (int j = 0; j < 4; j++)
                wmma::load_matrix_sync(bf_[j], &Ws[(wn * 64 + j * 16) * 72 + kk], 72);
            if constexpr (MODE == 1) {
                wmma::fragment<wmma::matrix_a, 16, 16, 16, half, wmma::col_major> af[2];
                wmma::load_matrix_sync(af[0], &As[kk * 72 + wm * 32], 72);
                wmma::load_matrix_sync(af[1], &As[kk * 72 + wm * 32 + 16], 72);
#pragma unroll
                for (int i = 0; i < 2; i++)
#pragma unroll
                    for (int j = 0; j < 4; j++)
                        wmma::mma_sync(acc[i][j], af[i], bf_[j], acc[i][j]);
            } else {
                wmma::fragment<wmma::matrix_a, 16, 16, 16, half, wmma::row_major> af[2];
                wmma::load_matrix_sync(af[0], &As[(wm * 32) * 72 + kk], 72);
                wmma::load_matrix_sync(af[1], &As[(wm * 32 + 16) * 72 + kk], 72);
#pragma unroll
                for (int i = 0; i < 2; i++)
#pragma unroll
                    for (int j = 0; j < 4; j++)
                        wmma::mma_sync(acc[i][j], af[i], bf_[j], acc[i][j]);
            }
        }
        __syncthreads();
        buf ^= 1;
    }

    // epilogue: stage fp32 C in smem, add bias, emit.
#pragma unroll
    for (int i = 0; i < 2; i++)
#pragma unroll
        for (int j = 0; j < 4; j++)
            wmma::store_matrix_sync(&Cs[(wm * 32 + i * 16) * 132 + wn * 64 + j * 16],
                                    acc[i][j], 132, wmma::mem_row_major);
    __syncthreads();
#pragma unroll
    for (int i = 0; i < 16; i++) {
        const int f = tid + 128 * i;
        const int row = f >> 5;
        const int cq = f & 31;
        const float4 v = *reinterpret_cast<const float4*>(&Cs[row * 132 + cq * 4]);
        const int mg = m0 + row;
        const int ng = nb + cq * 4;
        const float4 b4 = *reinterpret_cast<const float4*>(&bias[ng]);
        float4 o4;
        o4.x = v.x + b4.x; o4.y = v.y + b4.y;
        o4.z = v.z + b4.z; o4.w = v.w + b4.w;
        if constexpr (MODE == 2) {
            *reinterpret_cast<float4*>(
                outp + (size_t)z * 1048576 + (size_t)mg * 256 + ng) = o4;
        } else {
            __half2 lo, hi;
            lo.x = to_h(o4.x); lo.y = to_h(o4.y);
            hi.x = to_h(o4.z); hi.y = to_h(o4.w);
            uint2 pk;
            pk.x = *reinterpret_cast<uint32_t*>(&lo);
            pk.y = *reinterpret_cast<uint32_t*>(&hi);
            const int head = ng >> 5;
            hf* dst;
            if (isqk)
                dst = g_qkh[qkbr] + (size_t)(mg >> 6) * 16384 + (size_t)head * 2048
                    + (size_t)(mg & 63) * 32 + (ng & 31);
            else
                dst = g_v + (size_t)z * 1048576 + (size_t)head * 131072
                    + (size_t)mg * 32 + (ng & 31);
            *reinterpret_cast<uint2*>(dst) = pk;
        }
    }
}

// ---------------------------------------------------------------------------
// Kernel 3: axh — inline attn_h, then R[64][256-chunk] = attn_h @ V.
// Grid (8 n-chunks, 128 bh), 256 threads = 8 warps (2m x 4n).
// V tiles via cp.async overlapped with the inlined softmax.
// ---------------------------------------------------------------------------
__global__ void __launch_bounds__(256, 2) axh_kernel(const float* __restrict__ Bh)
{
    __shared__ hf Ah_s[64 * 72];         // 9.2 KB
    __shared__ hf Vs[64 * 264];          // 33.8 KB (aliased fp32 staging [64][132])
    __shared__ float sc[64 * 68];        // 17.4 KB score scratch
    const int bh = blockIdx.y;
    const int n0 = blockIdx.x * 256;
    const int tid = threadIdx.x;
    const int wid = tid >> 5;
    const int wm = wid >> 2;             // 0..1
    const int wn = wid & 3;              // 0..3

    // start async V loads (overlap with attention compute)
    {
        const hf* Vg = g_v + (size_t)bh * 131072 + n0;
#pragma unroll
        for (int i = 0; i < 8; i++) {
            const int f = tid + 256 * i;
            const int r = f >> 5, cc = (f & 31) * 8;
            cp_async16(&Vs[r * 264 + cc], Vg + (size_t)r * 2048 + cc);
        }
        CP_COMMIT();
    }

    // inline attention (axis 0) -> Ah_s
    attn_inline(g_qkh[0] + (size_t)bh * 2048, g_qkh[1] + (size_t)bh * 2048,
                Bh + (bh & 7) * 4096, Ah_s, sc);
    CP_WAIT(0);
    __syncthreads();

    wmma::fragment<wmma::accumulator, 16, 16, 16, float> acc[2][4];
#pragma unroll
    for (int i = 0; i < 2; i++)
#pragma unroll
        for (int j = 0; j < 4; j++) wmma::fill_fragment(acc[i][j], 0.f);

#pragma unroll
    for (int kk = 0; kk < 64; kk += 16) {
        wmma::fragment<wmma::matrix_a, 16, 16, 16, half, wmma::row_major> af[2];
        wmma::load_matrix_sync(af[0], &Ah_s[(wm * 32) * 72 + kk], 72);
        wmma::load_matrix_sync(af[1], &Ah_s[(wm * 32 + 16) * 72 + kk], 72);
        wmma::fragment<wmma::matrix_b, 16, 16, 16, half, wmma::row_major> bf_[4];
#pragma unroll
        for (int j = 0; j < 4; j++)
            wmma::load_matrix_sync(bf_[j], &Vs[kk * 264 + wn * 64 + j * 16], 264);
#pragma unroll
        for (int i = 0; i < 2; i++)
#pragma unroll
            for (int j = 0; j < 4; j++)
                wmma::mma_sync(acc[i][j], af[i], bf_[j], acc[i][j]);
    }
    __syncthreads();    // Vs dead -> staging

    float* St = reinterpret_cast<float*>(Vs);
    hf* Rg = g_r + (size_t)bh * 131072;
#pragma unroll
    for (int p = 0; p < 2; p++) {
        if ((wn >> 1) == p) {
#pragma unroll
            for (int i = 0; i < 2; i++)
#pragma unroll
                for (int j = 0; j < 4; j++)
                    wmma::store_matrix_sync(
                        &St[(wm * 32 + i * 16) * 132 + (wn & 1) * 64 + j * 16],
                        acc[i][j], 132, wmma::mem_row_major);
        }
        __syncthreads();
#pragma unroll
        for (int i = 0; i < 4; i++) {
            const int f = tid + 256 * i;
            const int row = f >> 4, c8 = (f & 15) * 8;
            const float4 v0 = *reinterpret_cast<const float4*>(&St[row * 132 + c8]);
            const float4 v1 = *reinterpret_cast<const float4*>(&St[row * 132 + c8 + 4]);
            __half2 pk_[4];
            pk_[0].x = to_h(v0.x); pk_[0].y = to_h(v0.y);
            pk_[1].x = to_h(v0.z); pk_[1].y = to_h(v0.w);
            pk_[2].x = to_h(v1.x); pk_[2].y = to_h(v1.y);
            pk_[3].x = to_h(v1.z); pk_[3].y = to_h(v1.w);
            *reinterpret_cast<uint4*>(Rg + (size_t)row * 2048 + n0 + p * 128 + c8) =
                *reinterpret_cast<uint4*>(pk_);
        }
        __syncthreads();
    }
}

// ---------------------------------------------------------------------------
// Kernel 4: axw — inline attn_w, then per h: [32 dv][64 w'] = R[h]^T @ attn_w.
// Grid (8 h-chunks, 128 bh), 256 threads = 8 warps, warp = one h.
// ---------------------------------------------------------------------------
__global__ void __launch_bounds__(256, 2) axw_kernel(const float* __restrict__ Bw)
{
    __shared__ hf Aw_s[64 * 72];         // 9.2 KB
    __shared__ hf Rs[8 * 2056];          // 32.1 KB (aliased fp32 staging)
    __shared__ float sc[64 * 68];        // 17.4 KB score scratch
    const int bh = blockIdx.y;
    const int hc = blockIdx.x;           // h chunk (8 h)
    const int tid = threadIdx.x;
    const int wid = tid >> 5;

    // start async R loads
    {
        const hf* Rg = g_r + (size_t)bh * 131072 + (size_t)(hc * 8) * 2048;
#pragma unroll
        for (int i = 0; i < 8; i++) {
            const int f = tid + 256 * i;
            const int hl = f >> 8, cc = (f & 255) * 8;
            cp_async16(&Rs[hl * 2056 + cc], Rg + (size_t)hl * 2048 + cc);
        }
        CP_COMMIT();
    }

    // inline attention (axis 1) -> Aw_s
    attn_inline(g_qkh[2] + (size_t)bh * 2048, g_qkh[3] + (size_t)bh * 2048,
                Bw + (bh & 7) * 4096, Aw_s, sc);
    CP_WAIT(0);
    __syncthreads();

    wmma::fragment<wmma::accumulator, 16, 16, 16, float> acc[2][4];
#pragma unroll
    for (int i = 0; i < 2; i++)
#pragma unroll
        for (int j = 0; j < 4; j++) wmma::fill_fragment(acc[i][j], 0.f);

    const hf* Ar = &Rs[wid * 2056];
#pragma unroll
    for (int kk = 0; kk < 64; kk += 16) {
        wmma::fragment<wmma::matrix_a, 16, 16, 16, half, wmma::col_major> af[2];
        wmma::load_matrix_sync(af[0], Ar + kk * 32, 32);
        wmma::load_matrix_sync(af[1], Ar + kk * 32 + 16, 32);
        wmma::fragment<wmma::matrix_b, 16, 16, 16, half, wmma::row_major> bf_[4];
#pragma unroll
        for (int j = 0; j < 4; j++)
            wmma::load_matrix_sync(bf_[j], &Aw_s[kk * 72 + j * 16], 72);
#pragma unroll
        for (int i = 0; i < 2; i++)
#pragma unroll
            for (int j = 0; j < 4; j++)
                wmma::mma_sync(acc[i][j], af[i], bf_[j], acc[i][j]);
    }
    __syncthreads();    // Rs dead -> staging

    float* St = reinterpret_cast<float*>(Rs);     // 4 slices of [64][32] fp32
    hf* outb = g_r2 + (size_t)(bh >> 3) * 1048576 + (bh & 7) * 32;
#pragma unroll
    for (int p = 0; p < 2; p++) {
        if ((wid >> 2) == p) {
            float* sl = St + (wid & 3) * 2048;
#pragma unroll
            for (int i = 0; i < 2; i++)
#pragma unroll
                for (int j = 0; j < 4; j++)
                    wmma::store_matrix_sync(sl + (j * 16) * 32 + i * 16,
                                            acc[i][j], 32, wmma::mem_col_major);
        }
        __syncthreads();
#pragma unroll
        for (int i = 0; i < 4; i++) {
            const int f = tid + 256 * i;
            const int hl = f >> 8;
            const int rem = f & 255;
            const int wp = rem >> 2, d8 = (rem & 3) * 8;
            const float* src = St + hl * 2048 + wp * 32 + d8;
            const float4 v0 = *reinterpret_cast<const float4*>(src);
            const float4 v1 = *reinterpret_cast<const float4*>(src + 4);
            __half2 pk_[4];
            pk_[0].x = to_h(v0.x); pk_[0].y = to_h(v0.y);
            pk_[1].x = to_h(v0.z); pk_[1].y = to_h(v0.w);
            pk_[2].x = to_h(v1.x); pk_[2].y = to_h(v1.y);
            pk_[3].x = to_h(v1.z); pk_[3].y = to_h(v1.w);
            const int h = hc * 8 + p * 4 + hl;
            *reinterpret_cast<uint4*>(
                outb + (size_t)(h * 64 + wp) * 256 + d8) =
                *reinterpret_cast<uint4*>(pk_);
        }
        __syncthreads();
    }
}

// ---------------------------------------------------------------------------
// Launch
// ---------------------------------------------------------------------------
extern "C" void kernel_launch(void* const* d_in, const int* in_sizes, int n_in,
                              void* d_out, int out_size)
{
    const float* x       = (const float*)d_in[0];
    const float* dw_qh_w = (const float*)d_in[1];
    const float* dw_qh_b = (const float*)d_in[2];
    const float* fc_qh_w = (const float*)d_in[3];
    const float* fc_qh_b = (const float*)d_in[4];
    const float* dw_kh_w = (const float*)d_in[5];
    const float* dw_kh_b = (const float*)d_in[6];
    const float* fc_kh_w = (const float*)d_in[7];
    const float* fc_kh_b = (const float*)d_in[8];
    const float* Bh      = (const float*)d_in[9];
    const float* dw_v_w  = (const float*)d_in[10];
    const float* dw_v_b  = (const float*)d_in[11];
    const float* fc_v_w  = (const float*)d_in[12];
    const float* fc_v_b  = (const float*)d_in[13];
    const float* dw_qw_w = (const float*)d_in[14];
    const float* dw_qw_b = (const float*)d_in[15];
    const float* fc_qw_w = (const float*)d_in[16];
    const float* fc_qw_b = (const float*)d_in[17];
    const float* dw_kw_w = (const float*)d_in[18];
    const float* dw_kw_b = (const float*)d_in[19];
    const float* fc_kw_w = (const float*)d_in[20];
    const float* fc_kw_b = (const float*)d_in[21];
    const float* Bw      = (const float*)d_in[22];
    const float* fc_o_w  = (const float*)d_in[23];
    const float* fc_o_b  = (const float*)d_in[24];
    float* out = (float*)d_out;

    conv_fused_kernel<<<dim3(Cc, Bb + 1), 256>>>(
        x, dw_v_w, dw_v_b,
        dw_qh_w, dw_qh_b, dw_kh_w, dw_kh_b,
        dw_qw_w, dw_qw_b, dw_kw_w, dw_kw_b,
        fc_qh_w, fc_kh_w, fc_qw_w, fc_kw_w, fc_v_w, fc_o_w);

    wmma_gemm_kernel<1><<<dim3(64, 2, Bb + 1), 128>>>(
        fc_qh_b, fc_kh_b, fc_qw_b, fc_kw_b, fc_v_b, nullptr);

    axh_kernel<<<dim3(8, Bb * Hh), 256>>>(Bh);
    axw_kernel<<<dim3(8, Bb * Hh), 256>>>(Bw);

    wmma_gemm_kernel<2><<<dim3(64, 2, Bb), 128>>>(
        fc_o_b, fc_o_b, fc_o_b, fc_o_b, fc_o_b, out);
}